// round 1
// baseline (speedup 1.0000x reference)
#include <cuda_runtime.h>
#include <cuda_bf16.h>

#define NN 1024
#define MM 1024
#define DDIM 512

// Scratch (allocation-free rule: __device__ globals)
__device__ float g_qp[NN * DDIM];
__device__ float g_kp[MM * DDIM];
__device__ float g_vp[MM * DDIM];
__device__ float g_sc[NN * MM];

__device__ __forceinline__ float fast_tanh(float x) {
    float y;
    asm("tanh.approx.f32 %0, %1;" : "=f"(y) : "f"(x));
    return y;
}

// ---------------------------------------------------------------------------
// Projections: out = X @ W^T + b   (NT gemm, both operands k-contiguous)
// tile 64x64, k-chunk 16, 256 threads, 4x4 micro-tile. blockIdx.z selects q/k/v.
// grid (512/64=8, 1024/64=16, 3)
// ---------------------------------------------------------------------------
__global__ void proj_kernel(const float* __restrict__ q, const float* __restrict__ k,
                            const float* __restrict__ v,
                            const float* __restrict__ Wq, const float* __restrict__ bq,
                            const float* __restrict__ Wk, const float* __restrict__ bk,
                            const float* __restrict__ Wv, const float* __restrict__ bv)
{
    __shared__ float As[16][68];  // [kk][i]
    __shared__ float Bs[16][68];  // [kk][j]
    const float *X, *W, *B;
    float* out;
    if (blockIdx.z == 0)      { X = q; W = Wq; B = bq; out = g_qp; }
    else if (blockIdx.z == 1) { X = k; W = Wk; B = bk; out = g_kp; }
    else                      { X = v; W = Wv; B = bv; out = g_vp; }

    const int tid = threadIdx.x;
    const int tx = tid & 15, ty = tid >> 4;
    const int bi = blockIdx.y * 64, bj = blockIdx.x * 64;
    const int lr = tid >> 2, lc = (tid & 3) << 2;

    float acc[4][4];
#pragma unroll
    for (int u = 0; u < 4; u++)
#pragma unroll
        for (int w = 0; w < 4; w++) acc[u][w] = 0.f;

    for (int k0 = 0; k0 < DDIM; k0 += 16) {
        float4 a4 = *(const float4*)(X + (size_t)(bi + lr) * DDIM + k0 + lc);
        float4 b4 = *(const float4*)(W + (size_t)(bj + lr) * DDIM + k0 + lc);
        As[lc + 0][lr] = a4.x; As[lc + 1][lr] = a4.y;
        As[lc + 2][lr] = a4.z; As[lc + 3][lr] = a4.w;
        Bs[lc + 0][lr] = b4.x; Bs[lc + 1][lr] = b4.y;
        Bs[lc + 2][lr] = b4.z; Bs[lc + 3][lr] = b4.w;
        __syncthreads();
#pragma unroll
        for (int kk = 0; kk < 16; kk++) {
            float4 ra = *(const float4*)&As[kk][ty << 2];
            float4 rb = *(const float4*)&Bs[kk][tx << 2];
            float fa[4] = {ra.x, ra.y, ra.z, ra.w};
            float fb[4] = {rb.x, rb.y, rb.z, rb.w};
#pragma unroll
            for (int u = 0; u < 4; u++)
#pragma unroll
                for (int w = 0; w < 4; w++) acc[u][w] += fa[u] * fb[w];
        }
        __syncthreads();
    }
#pragma unroll
    for (int u = 0; u < 4; u++) {
        int row = bi + (ty << 2) + u;
#pragma unroll
        for (int w = 0; w < 4; w++) {
            int col = bj + (tx << 2) + w;
            out[(size_t)row * DDIM + col] = acc[u][w] + B[col];
        }
    }
}

// ---------------------------------------------------------------------------
// Scores: sc[n,m] = sum_d Ww[d]*tanh(qp[n,d]+kp[m,d]) + bw; masked -> -1e6.
// MUFU-bound; tiles only keep LDS/LDG off the critical path.
// tile 32(n) x 32(m), d-chunk 16, 128 threads, 4(n)x2(m) micro.
// grid (1024/32=32 m-tiles, 32 n-tiles)
// ---------------------------------------------------------------------------
__global__ void score_kernel(const float* __restrict__ Ww, const float* __restrict__ bw,
                             const int* __restrict__ mask)
{
    __shared__ float qs[16][36];  // [dd][n]
    __shared__ float ks[16][36];  // [dd][m]
    __shared__ float ws[16];

    const int tid = threadIdx.x;
    const int tx = tid & 15;      // m pair
    const int ty = tid >> 4;      // n quad (0..7)
    const int bn = blockIdx.y * 32, bm = blockIdx.x * 32;
    const int lr = tid >> 2, lc = (tid & 3) << 2;  // lr 0..31

    float acc[4][2];
#pragma unroll
    for (int u = 0; u < 4; u++) { acc[u][0] = 0.f; acc[u][1] = 0.f; }

    for (int d0 = 0; d0 < DDIM; d0 += 16) {
        float4 a4 = *(const float4*)(g_qp + (size_t)(bn + lr) * DDIM + d0 + lc);
        float4 b4 = *(const float4*)(g_kp + (size_t)(bm + lr) * DDIM + d0 + lc);
        qs[lc + 0][lr] = a4.x; qs[lc + 1][lr] = a4.y;
        qs[lc + 2][lr] = a4.z; qs[lc + 3][lr] = a4.w;
        ks[lc + 0][lr] = b4.x; ks[lc + 1][lr] = b4.y;
        ks[lc + 2][lr] = b4.z; ks[lc + 3][lr] = b4.w;
        if (tid < 16) ws[tid] = Ww[d0 + tid];
        __syncthreads();
#pragma unroll
        for (int dd = 0; dd < 16; dd++) {
            float w = ws[dd];
            float4 rq = *(const float4*)&qs[dd][ty << 2];
            float2 rk = *(const float2*)&ks[dd][tx << 1];
            float fq[4] = {rq.x, rq.y, rq.z, rq.w};
            float fk[2] = {rk.x, rk.y};
#pragma unroll
            for (int u = 0; u < 4; u++)
#pragma unroll
                for (int j = 0; j < 2; j++)
                    acc[u][j] += w * fast_tanh(fq[u] + fk[j]);
        }
        __syncthreads();
    }

    const float b0 = bw[0];
#pragma unroll
    for (int u = 0; u < 4; u++) {
        int n = bn + (ty << 2) + u;
#pragma unroll
        for (int j = 0; j < 2; j++) {
            int m = bm + (tx << 1) + j;
            float s = acc[u][j] + b0;
            g_sc[(size_t)n * MM + m] = mask[(size_t)n * MM + m] ? s : -1000000.0f;
        }
    }
}

// ---------------------------------------------------------------------------
// Row softmax over M=1024. One block (256 threads) per row, 4 elements/thread.
// ---------------------------------------------------------------------------
__global__ void softmax_kernel()
{
    const int n = blockIdx.x;
    float* row = g_sc + (size_t)n * MM;
    const int tid = threadIdx.x;
    __shared__ float red[8];

    float v0[4];
    float mx = -3.0e38f;
#pragma unroll
    for (int i = 0; i < 4; i++) {
        v0[i] = row[tid + (i << 8)];
        mx = fmaxf(mx, v0[i]);
    }
#pragma unroll
    for (int o = 16; o > 0; o >>= 1) mx = fmaxf(mx, __shfl_xor_sync(0xffffffffu, mx, o));
    if ((tid & 31) == 0) red[tid >> 5] = mx;
    __syncthreads();
    mx = red[0];
#pragma unroll
    for (int i = 1; i < 8; i++) mx = fmaxf(mx, red[i]);

    float sum = 0.f;
#pragma unroll
    for (int i = 0; i < 4; i++) {
        float e = __expf(v0[i] - mx);
        v0[i] = e;
        sum += e;
    }
#pragma unroll
    for (int o = 16; o > 0; o >>= 1) sum += __shfl_xor_sync(0xffffffffu, sum, o);
    __syncthreads();
    if ((tid & 31) == 0) red[tid >> 5] = sum;
    __syncthreads();
    sum = red[0];
#pragma unroll
    for (int i = 1; i < 8; i++) sum += red[i];

    float inv = 1.0f / sum;
#pragma unroll
    for (int i = 0; i < 4; i++) row[tid + (i << 8)] = v0[i] * inv;
}

// ---------------------------------------------------------------------------
// Context: out[n,d] = sum_m attn[n,m] * vp[m,d]   (NN gemm)
// tile 64(n) x 64(d), m-chunk 16, 256 threads, 4x4 micro. grid (8,16)
// ---------------------------------------------------------------------------
__global__ void ctx_kernel(float* __restrict__ out)
{
    __shared__ float As[16][68];  // [mm][n] (transposed)
    __shared__ float Bs[16][68];  // [mm][d]

    const int tid = threadIdx.x;
    const int tx = tid & 15, ty = tid >> 4;
    const int bn = blockIdx.y * 64, bd = blockIdx.x * 64;
    const int alr = tid >> 2, alc = (tid & 3) << 2;   // attn tile loader
    const int blr = tid >> 4, blc = (tid & 15) << 2;  // vp tile loader

    float acc[4][4];
#pragma unroll
    for (int u = 0; u < 4; u++)
#pragma unroll
        for (int w = 0; w < 4; w++) acc[u][w] = 0.f;

    for (int m0 = 0; m0 < MM; m0 += 16) {
        float4 a4 = *(const float4*)(g_sc + (size_t)(bn + alr) * MM + m0 + alc);
        As[alc + 0][alr] = a4.x; As[alc + 1][alr] = a4.y;
        As[alc + 2][alr] = a4.z; As[alc + 3][alr] = a4.w;
        float4 b4 = *(const float4*)(g_vp + (size_t)(m0 + blr) * DDIM + bd + blc);
        *(float4*)&Bs[blr][blc] = b4;
        __syncthreads();
#pragma unroll
        for (int mm = 0; mm < 16; mm++) {
            float4 ra = *(const float4*)&As[mm][ty << 2];
            float4 rb = *(const float4*)&Bs[mm][tx << 2];
            float fa[4] = {ra.x, ra.y, ra.z, ra.w};
            float fb[4] = {rb.x, rb.y, rb.z, rb.w};
#pragma unroll
            for (int u = 0; u < 4; u++)
#pragma unroll
                for (int w = 0; w < 4; w++) acc[u][w] += fa[u] * fb[w];
        }
        __syncthreads();
    }
#pragma unroll
    for (int u = 0; u < 4; u++) {
        int row = bn + (ty << 2) + u;
#pragma unroll
        for (int w = 0; w < 4; w++) {
            int col = bd + (tx << 2) + w;
            out[(size_t)row * DDIM + col] = acc[u][w];
        }
    }
}

// ---------------------------------------------------------------------------
extern "C" void kernel_launch(void* const* d_in, const int* in_sizes, int n_in,
                              void* d_out, int out_size)
{
    const float* q    = (const float*)d_in[0];
    const float* k    = (const float*)d_in[1];
    const float* v    = (const float*)d_in[2];
    const int*   mask = (const int*)d_in[3];
    const float* Wq   = (const float*)d_in[4];
    const float* bq   = (const float*)d_in[5];
    const float* Wk   = (const float*)d_in[6];
    const float* bk   = (const float*)d_in[7];
    const float* Wv   = (const float*)d_in[8];
    const float* bv   = (const float*)d_in[9];
    const float* Ww   = (const float*)d_in[10];
    const float* bw   = (const float*)d_in[11];
    float* out = (float*)d_out;

    proj_kernel<<<dim3(8, 16, 3), 256>>>(q, k, v, Wq, bq, Wk, bk, Wv, bv);
    score_kernel<<<dim3(32, 32), 128>>>(Ww, bw, mask);
    softmax_kernel<<<1024, 256>>>();
    ctx_kernel<<<dim3(8, 16), 256>>>(out);
}

// round 2
// speedup vs baseline: 1.0692x; 1.0692x over previous
#include <cuda_runtime.h>
#include <cuda_bf16.h>
#include <cuda_fp16.h>

#define NN 1024
#define MM 1024
#define DDIM 512

// Scratch (allocation-free rule: __device__ globals)
__device__ float g_qp[NN * DDIM];
__device__ float g_kp[MM * DDIM];
__device__ float g_vp[MM * DDIM];
__device__ float g_sc[NN * MM];

__device__ __forceinline__ unsigned tanh2_approx(unsigned x) {
    unsigned y;
    asm("tanh.approx.f16x2 %0, %1;" : "=r"(y) : "r"(x));
    return y;
}

// ---------------------------------------------------------------------------
// Projections: out = X @ W^T + b   (NT gemm, both operands k-contiguous)
// tile 64x64, k-chunk 16, 256 threads, 4x4 micro-tile. blockIdx.z selects q/k/v.
// grid (512/64=8, 1024/64=16, 3)
// ---------------------------------------------------------------------------
__global__ void proj_kernel(const float* __restrict__ q, const float* __restrict__ k,
                            const float* __restrict__ v,
                            const float* __restrict__ Wq, const float* __restrict__ bq,
                            const float* __restrict__ Wk, const float* __restrict__ bk,
                            const float* __restrict__ Wv, const float* __restrict__ bv)
{
    __shared__ float As[16][68];  // [kk][i]
    __shared__ float Bs[16][68];  // [kk][j]
    const float *X, *W, *B;
    float* out;
    if (blockIdx.z == 0)      { X = q; W = Wq; B = bq; out = g_qp; }
    else if (blockIdx.z == 1) { X = k; W = Wk; B = bk; out = g_kp; }
    else                      { X = v; W = Wv; B = bv; out = g_vp; }

    const int tid = threadIdx.x;
    const int tx = tid & 15, ty = tid >> 4;
    const int bi = blockIdx.y * 64, bj = blockIdx.x * 64;
    const int lr = tid >> 2, lc = (tid & 3) << 2;

    float acc[4][4];
#pragma unroll
    for (int u = 0; u < 4; u++)
#pragma unroll
        for (int w = 0; w < 4; w++) acc[u][w] = 0.f;

    for (int k0 = 0; k0 < DDIM; k0 += 16) {
        float4 a4 = *(const float4*)(X + (size_t)(bi + lr) * DDIM + k0 + lc);
        float4 b4 = *(const float4*)(W + (size_t)(bj + lr) * DDIM + k0 + lc);
        As[lc + 0][lr] = a4.x; As[lc + 1][lr] = a4.y;
        As[lc + 2][lr] = a4.z; As[lc + 3][lr] = a4.w;
        Bs[lc + 0][lr] = b4.x; Bs[lc + 1][lr] = b4.y;
        Bs[lc + 2][lr] = b4.z; Bs[lc + 3][lr] = b4.w;
        __syncthreads();
#pragma unroll
        for (int kk = 0; kk < 16; kk++) {
            float4 ra = *(const float4*)&As[kk][ty << 2];
            float4 rb = *(const float4*)&Bs[kk][tx << 2];
            float fa[4] = {ra.x, ra.y, ra.z, ra.w};
            float fb[4] = {rb.x, rb.y, rb.z, rb.w};
#pragma unroll
            for (int u = 0; u < 4; u++)
#pragma unroll
                for (int w = 0; w < 4; w++) acc[u][w] += fa[u] * fb[w];
        }
        __syncthreads();
    }
#pragma unroll
    for (int u = 0; u < 4; u++) {
        int row = bi + (ty << 2) + u;
#pragma unroll
        for (int w = 0; w < 4; w++) {
            int col = bj + (tx << 2) + w;
            out[(size_t)row * DDIM + col] = acc[u][w] + B[col];
        }
    }
}

// ---------------------------------------------------------------------------
// Scores: sc[n,m] = sum_d Ww[d]*tanh(qp[n,d]+kp[m,d]) + bw; masked -> -1e6.
// MUFU-bound: use tanh.approx.f16x2 to do 2 tanh per MUFU op.
// tile 32(n) x 32(m), d-chunk 16, 128 threads, 4(n)x2(m) micro.
// grid (32 m-tiles, 32 n-tiles)
// ---------------------------------------------------------------------------
__global__ void score_kernel(const float* __restrict__ Ww, const float* __restrict__ bw,
                             const int* __restrict__ mask)
{
    __shared__ float qs[16][36];  // [dd][n]
    __shared__ float ks[16][36];  // [dd][m]
    __shared__ float ws[16];

    const int tid = threadIdx.x;
    const int tx = tid & 15;      // m pair
    const int ty = tid >> 4;      // n quad (0..7)
    const int bn = blockIdx.y * 32, bm = blockIdx.x * 32;
    const int lr = tid >> 2, lc = (tid & 3) << 2;  // lr 0..31

    float acc[4][2];
#pragma unroll
    for (int u = 0; u < 4; u++) { acc[u][0] = 0.f; acc[u][1] = 0.f; }

    for (int d0 = 0; d0 < DDIM; d0 += 16) {
        float4 a4 = *(const float4*)(g_qp + (size_t)(bn + lr) * DDIM + d0 + lc);
        float4 b4 = *(const float4*)(g_kp + (size_t)(bm + lr) * DDIM + d0 + lc);
        qs[lc + 0][lr] = a4.x; qs[lc + 1][lr] = a4.y;
        qs[lc + 2][lr] = a4.z; qs[lc + 3][lr] = a4.w;
        ks[lc + 0][lr] = b4.x; ks[lc + 1][lr] = b4.y;
        ks[lc + 2][lr] = b4.z; ks[lc + 3][lr] = b4.w;
        if (tid < 16) ws[tid] = Ww[d0 + tid];
        __syncthreads();
#pragma unroll
        for (int dd = 0; dd < 16; dd++) {
            float w = ws[dd];
            float4 rq = *(const float4*)&qs[dd][ty << 2];
            float2 rk = *(const float2*)&ks[dd][tx << 1];
            float fq[4] = {rq.x, rq.y, rq.z, rq.w};
#pragma unroll
            for (int u = 0; u < 4; u++) {
                __half2 h = __floats2half2_rn(fq[u] + rk.x, fq[u] + rk.y);
                unsigned t2 = tanh2_approx(*(unsigned*)&h);
                float2 tf = __half22float2(*(__half2*)&t2);
                acc[u][0] += w * tf.x;
                acc[u][1] += w * tf.y;
            }
        }
        __syncthreads();
    }

    const float b0 = bw[0];
#pragma unroll
    for (int u = 0; u < 4; u++) {
        int n = bn + (ty << 2) + u;
#pragma unroll
        for (int j = 0; j < 2; j++) {
            int m = bm + (tx << 1) + j;
            float s = acc[u][j] + b0;
            g_sc[(size_t)n * MM + m] = mask[(size_t)n * MM + m] ? s : -1000000.0f;
        }
    }
}

// ---------------------------------------------------------------------------
// Row softmax over M=1024. One block (256 threads) per row, 4 elements/thread.
// ---------------------------------------------------------------------------
__global__ void softmax_kernel()
{
    const int n = blockIdx.x;
    float* row = g_sc + (size_t)n * MM;
    const int tid = threadIdx.x;
    __shared__ float red[8];

    float v0[4];
    float mx = -3.0e38f;
#pragma unroll
    for (int i = 0; i < 4; i++) {
        v0[i] = row[tid + (i << 8)];
        mx = fmaxf(mx, v0[i]);
    }
#pragma unroll
    for (int o = 16; o > 0; o >>= 1) mx = fmaxf(mx, __shfl_xor_sync(0xffffffffu, mx, o));
    if ((tid & 31) == 0) red[tid >> 5] = mx;
    __syncthreads();
    mx = red[0];
#pragma unroll
    for (int i = 1; i < 8; i++) mx = fmaxf(mx, red[i]);

    float sum = 0.f;
#pragma unroll
    for (int i = 0; i < 4; i++) {
        float e = __expf(v0[i] - mx);
        v0[i] = e;
        sum += e;
    }
#pragma unroll
    for (int o = 16; o > 0; o >>= 1) sum += __shfl_xor_sync(0xffffffffu, sum, o);
    __syncthreads();
    if ((tid & 31) == 0) red[tid >> 5] = sum;
    __syncthreads();
    sum = red[0];
#pragma unroll
    for (int i = 1; i < 8; i++) sum += red[i];

    float inv = 1.0f / sum;
#pragma unroll
    for (int i = 0; i < 4; i++) row[tid + (i << 8)] = v0[i] * inv;
}

// ---------------------------------------------------------------------------
// Context: out[n,d] = sum_m attn[n,m] * vp[m,d]
// tile 64(n) x 32(d), m-chunk 32, 128 threads, 4x4 micro.
// grid (512/32=16 d-tiles, 1024/64=16 n-tiles) = 256 CTAs -> >=2 CTAs/SM.
// ---------------------------------------------------------------------------
__global__ void ctx_kernel(float* __restrict__ out)
{
    __shared__ float As[32][68];  // [mm][n] (transposed attn)
    __shared__ float Bs[32][36];  // [mm][d]

    const int tid = threadIdx.x;
    const int tx = tid & 7;       // d micro (8 * 4 = 32)
    const int ty = tid >> 3;      // n micro (16 * 4 = 64)
    const int bn = blockIdx.y * 64, bd = blockIdx.x * 32;

    float acc[4][4];
#pragma unroll
    for (int u = 0; u < 4; u++)
#pragma unroll
        for (int w = 0; w < 4; w++) acc[u][w] = 0.f;

    for (int m0 = 0; m0 < MM; m0 += 32) {
        // attn tile [64n x 32m] -> As[m][n] transposed: 4 float4 per thread
#pragma unroll
        for (int i = 0; i < 4; i++) {
            int idx = tid + (i << 7);        // 0..511
            int row = idx >> 3;              // n 0..63
            int c4  = (idx & 7) << 2;        // m 0,4,..28
            float4 a4 = *(const float4*)(g_sc + (size_t)(bn + row) * MM + m0 + c4);
            As[c4 + 0][row] = a4.x; As[c4 + 1][row] = a4.y;
            As[c4 + 2][row] = a4.z; As[c4 + 3][row] = a4.w;
        }
        // vp tile [32m x 32d]: 2 float4 per thread
#pragma unroll
        for (int i = 0; i < 2; i++) {
            int idx = tid + (i << 7);        // 0..255
            int row = idx >> 3;              // m 0..31
            int c4  = (idx & 7) << 2;        // d
            *(float4*)&Bs[row][c4] =
                *(const float4*)(g_vp + (size_t)(m0 + row) * DDIM + bd + c4);
        }
        __syncthreads();
#pragma unroll
        for (int mm = 0; mm < 32; mm++) {
            float4 ra = *(const float4*)&As[mm][ty << 2];
            float4 rb = *(const float4*)&Bs[mm][tx << 2];
            float fa[4] = {ra.x, ra.y, ra.z, ra.w};
            float fb[4] = {rb.x, rb.y, rb.z, rb.w};
#pragma unroll
            for (int u = 0; u < 4; u++)
#pragma unroll
                for (int w = 0; w < 4; w++) acc[u][w] += fa[u] * fb[w];
        }
        __syncthreads();
    }
#pragma unroll
    for (int u = 0; u < 4; u++) {
        int row = bn + (ty << 2) + u;
#pragma unroll
        for (int w = 0; w < 4; w++) {
            int col = bd + (tx << 2) + w;
            out[(size_t)row * DDIM + col] = acc[u][w];
        }
    }
}

// ---------------------------------------------------------------------------
extern "C" void kernel_launch(void* const* d_in, const int* in_sizes, int n_in,
                              void* d_out, int out_size)
{
    const float* q    = (const float*)d_in[0];
    const float* k    = (const float*)d_in[1];
    const float* v    = (const float*)d_in[2];
    const int*   mask = (const int*)d_in[3];
    const float* Wq   = (const float*)d_in[4];
    const float* bq   = (const float*)d_in[5];
    const float* Wk   = (const float*)d_in[6];
    const float* bk   = (const float*)d_in[7];
    const float* Wv   = (const float*)d_in[8];
    const float* bv   = (const float*)d_in[9];
    const float* Ww   = (const float*)d_in[10];
    const float* bw   = (const float*)d_in[11];
    float* out = (float*)d_out;

    proj_kernel<<<dim3(8, 16, 3), 256>>>(q, k, v, Wq, bq, Wk, bk, Wv, bv);
    score_kernel<<<dim3(32, 32), 128>>>(Ww, bw, mask);
    softmax_kernel<<<1024, 256>>>();
    ctx_kernel<<<dim3(16, 16), 128>>>(out);
}